// round 3
// baseline (speedup 1.0000x reference)
#include <cuda_runtime.h>
#include <math.h>

// Problem constants (fixed-shape problem: B=128, S=512, L=64)
#define BB 128
#define SB 512
#define LL 64
#define NPAIR (BB*SB)        // 65536 (b-major: p = b*S + s)
#define LDE 68               // padded smem row stride (floats), 16B aligned rows
#define GRID_MAIN 512
#define TILES_PER_BLK 2      // 512*2 = 1024 tiles of 64 pairs

__device__ float g_alpha_part[GRID_MAIN * LL];
__device__ float g_score_part[BB];

// ---- packed f32x2 helpers (Blackwell FFMA2) ----
__device__ __forceinline__ unsigned long long pk2(float lo, float hi) {
    unsigned long long r;
    asm("mov.b64 %0, {%1,%2};" : "=l"(r) : "f"(lo), "f"(hi));
    return r;
}
__device__ __forceinline__ void fma2(unsigned long long &d, unsigned long long a, unsigned long long b) {
    asm("fma.rn.f32x2 %0, %1, %2, %0;" : "+l"(d) : "l"(a), "l"(b));
}
__device__ __forceinline__ float2 up2(unsigned long long v) {
    float2 r;
    asm("mov.b64 {%0,%1}, %2;" : "=f"(r.x), "=f"(r.y) : "l"(v));
    return r;
}

// ============================================================================
// k_main: alpha_i partials.
//   For each pair p=(b,s): v_i = sum_j exp(T[i,j]) * exp(emit[p,j]);
//   c_i = log(v_i); accumulate w_p * c_i where w_p = (b != 0) && mask[p].
//   (b != 0 because the reference's inc_mask zeroes column 0 of (S,B), i.e.
//    batch 0 at every s.)
// NOTE: mask arrives as int32 (bool is materialized as i32 by the harness).
// Tiled as (64 pairs) x (64 outputs) x (K=64) fp32 GEMM with FFMA2.
// ============================================================================
__global__ void __launch_bounds__(256, 4)
k_main(const float* __restrict__ emit,
       const int* __restrict__ mask,
       const float* __restrict__ trans) {
    __shared__ __align__(16) float sT[64 * LDE];   // sT[k*LDE + i] = exp(T[i][k])
    __shared__ __align__(16) float sE[64 * LDE];   // sE[k*LDE + m] = exp(emit[pair m][k])
    __shared__ float sRed[64 * 17];

    const int tid = threadIdx.x;

    // Load + exp + transpose T (once per block).
#pragma unroll
    for (int r = 0; r < 16; r++) {
        int idx = tid + 256 * r;                    // idx = i*64 + k
        sT[(idx & 63) * LDE + (idx >> 6)] = __expf(trans[idx]);
    }

    const int tx = tid & 15;          // output-column group (4 i's)
    const int ty = tid >> 4;          // pair-row group (4 m's)
    const int lm = tid >> 2;          // load: row m (0..63), 4 threads per row
    const int lk = (tid & 3) * 16;    // load: k-base

    float accA = 0.0f;                // only meaningful for tid < 64

    for (int it = 0; it < TILES_PER_BLK; it++) {
        const int t = blockIdx.x * TILES_PER_BLK + it;
        const int pbase = t * 64;

        // Load 16 contiguous floats of row (pbase+lm), k = lk..lk+15
        const float4* src = reinterpret_cast<const float4*>(emit + (pbase + lm) * LL + lk);
        float4 f0 = src[0], f1 = src[1], f2 = src[2], f3 = src[3];
        float ev[16] = {f0.x, f0.y, f0.z, f0.w, f1.x, f1.y, f1.z, f1.w,
                        f2.x, f2.y, f2.z, f2.w, f3.x, f3.y, f3.z, f3.w};

        // Inclusion weights for this thread's 4 pair-rows (mask is int32).
        const int p0 = pbase + 4 * ty;
        float w0 = ((p0 + 0) >= SB && mask[p0 + 0] != 0) ? 1.0f : 0.0f;
        float w1 = ((p0 + 1) >= SB && mask[p0 + 1] != 0) ? 1.0f : 0.0f;
        float w2 = ((p0 + 2) >= SB && mask[p0 + 2] != 0) ? 1.0f : 0.0f;
        float w3 = ((p0 + 3) >= SB && mask[p0 + 3] != 0) ? 1.0f : 0.0f;

#pragma unroll
        for (int u = 0; u < 16; u++)
            sE[(lk + u) * LDE + lm] = __expf(ev[u]);
        __syncthreads();   // sT (first iter) + sE ready

        // 4x4 register tile: acc[mpair][i], mpair0=(m0,m1), mpair1=(m2,m3)
        unsigned long long a00 = 0ull, a01 = 0ull, a02 = 0ull, a03 = 0ull;
        unsigned long long a10 = 0ull, a11 = 0ull, a12 = 0ull, a13 = 0ull;
        const float* pT = sT + 4 * tx;
        const float* pE = sE + 4 * ty;
#pragma unroll 8
        for (int k = 0; k < 64; k++) {
            float4 tf = *reinterpret_cast<const float4*>(pT + k * LDE);
            ulonglong2 ef = *reinterpret_cast<const ulonglong2*>(pE + k * LDE);
            unsigned long long t0 = pk2(tf.x, tf.x);
            unsigned long long t1 = pk2(tf.y, tf.y);
            unsigned long long t2 = pk2(tf.z, tf.z);
            unsigned long long t3 = pk2(tf.w, tf.w);
            fma2(a00, ef.x, t0); fma2(a10, ef.y, t0);
            fma2(a01, ef.x, t1); fma2(a11, ef.y, t1);
            fma2(a02, ef.x, t2); fma2(a12, ef.y, t2);
            fma2(a03, ef.x, t3); fma2(a13, ef.y, t3);
        }

        // Epilogue: c = log(v), weight by inclusion mask, reduce over pairs.
        float2 u0, u1;
        u0 = up2(a00); u1 = up2(a10);
        float r0 = w0 * __logf(u0.x) + w1 * __logf(u0.y) + w2 * __logf(u1.x) + w3 * __logf(u1.y);
        u0 = up2(a01); u1 = up2(a11);
        float r1 = w0 * __logf(u0.x) + w1 * __logf(u0.y) + w2 * __logf(u1.x) + w3 * __logf(u1.y);
        u0 = up2(a02); u1 = up2(a12);
        float r2 = w0 * __logf(u0.x) + w1 * __logf(u0.y) + w2 * __logf(u1.x) + w3 * __logf(u1.y);
        u0 = up2(a03); u1 = up2(a13);
        float r3 = w0 * __logf(u0.x) + w1 * __logf(u0.y) + w2 * __logf(u1.x) + w3 * __logf(u1.y);

        sRed[(4 * tx + 0) * 17 + ty] = r0;
        sRed[(4 * tx + 1) * 17 + ty] = r1;
        sRed[(4 * tx + 2) * 17 + ty] = r2;
        sRed[(4 * tx + 3) * 17 + ty] = r3;
        __syncthreads();   // also guarantees all sE reads of this tile finished

        if (tid < 64) {
            float s = 0.0f;
#pragma unroll
            for (int y2 = 0; y2 < 16; y2++) s += sRed[tid * 17 + y2];
            accA += s;
        }
        // Next iteration's sE stores are safe: every thread passed the barrier
        // above, so all sE reads of this tile are complete. sRed is rewritten
        // only after the next tile's barrier.
    }

    if (tid < 64) g_alpha_part[blockIdx.x * LL + tid] = accA;
}

// ============================================================================
// k_score: one block per batch b.
//   score_b = sum_{s: mask} ( emit[b,s,lab[s]] + (s>0)*T[lab[s-1],lab[s]] )
//           + strans[lab[0]] + etrans[lab[count-1]]
// mask is int32.
// ============================================================================
__global__ void __launch_bounds__(256)
k_score(const float* __restrict__ emit,
        const int* __restrict__ labels,
        const int* __restrict__ mask,
        const float* __restrict__ trans,
        const float* __restrict__ strans,
        const float* __restrict__ etrans) {
    const int b = blockIdx.x;
    const int tid = threadIdx.x;
    float acc = 0.0f;
    int cnt = 0;
#pragma unroll
    for (int s = tid; s < SB; s += 256) {
        int lab  = labels[b * SB + s];
        int labp = (s > 0) ? labels[b * SB + s - 1] : 0;
        int mm   = mask[b * SB + s];
        if (mm != 0) {
            float v = emit[(b * SB + s) * LL + lab];
            if (s > 0) v += trans[labp * LL + lab];
            acc += v;
            cnt++;
        }
    }
    __shared__ float rA[256];
    __shared__ int rC[256];
    rA[tid] = acc;
    rC[tid] = cnt;
    __syncthreads();
#pragma unroll
    for (int o = 128; o > 0; o >>= 1) {
        if (tid < o) { rA[tid] += rA[tid + o]; rC[tid] += rC[tid + o]; }
        __syncthreads();
    }
    if (tid == 0) {
        int ends = rC[0] - 1;
        float tot = rA[0] + strans[labels[b * SB + 0]] + etrans[labels[b * SB + ends]];
        g_score_part[b] = tot;
    }
}

// ============================================================================
// k_final: deterministic double-precision combine + stable logsumexp.
//   alpha_i = emit[0,0,i] + sum_blocks g_alpha_part; logZ = LSE(alpha);
//   out = (logZ - sum_b score_b) / B
// 256 threads: 4 threads per alpha lane, each covers a fixed quarter of the
// 512 block-partials (deterministic order), then fixed 4-way combine.
// ============================================================================
__global__ void __launch_bounds__(256)
k_final(const float* __restrict__ emit, float* __restrict__ out) {
    __shared__ double sP[4][64];
    __shared__ double sM[64];
    const int i = threadIdx.x & 63;     // alpha lane
    const int q = threadIdx.x >> 6;     // quarter 0..3

    double part = 0.0;
    const int blk0 = q * (GRID_MAIN / 4);
#pragma unroll 4
    for (int blk = blk0; blk < blk0 + GRID_MAIN / 4; blk++)
        part += (double)g_alpha_part[blk * LL + i];
    sP[q][i] = part;
    __syncthreads();

    if (threadIdx.x < 64) {
        double a = (double)emit[i] + ((sP[0][i] + sP[1][i]) + (sP[2][i] + sP[3][i]));
        sM[i] = a;
        sP[0][i] = a;   // stash for the exp pass
    }
    __syncthreads();
    // max reduce over 64 (threads 0..63)
#pragma unroll
    for (int o = 32; o > 0; o >>= 1) {
        if (threadIdx.x < o) sM[threadIdx.x] = fmax(sM[threadIdx.x], sM[threadIdx.x + o]);
        __syncthreads();
    }
    double mx = sM[0];
    __syncthreads();
    if (threadIdx.x < 64) sM[i] = exp(sP[0][i] - mx);
    __syncthreads();
#pragma unroll
    for (int o = 32; o > 0; o >>= 1) {
        if (threadIdx.x < o) sM[threadIdx.x] += sM[threadIdx.x + o];
        __syncthreads();
    }

    if (threadIdx.x == 0) {
        double logZ = mx + log(sM[0]);
        double sc = 0.0;
        for (int b = 0; b < BB; b++) sc += (double)g_score_part[b];
        out[0] = (float)((logZ - sc) / (double)BB);
    }
}

// ============================================================================
// kernel_launch
// Inputs (metadata order): emit f32[B,S,L], labels i32[B,S], mask i32[B,S]
// (bool materialized as int32), transitions f32[L,L], strans f32[L],
// etrans f32[L].  Output: f32[1]
// ============================================================================
extern "C" void kernel_launch(void* const* d_in, const int* in_sizes, int n_in,
                              void* d_out, int out_size) {
    const float* emit   = (const float*)d_in[0];
    const int*   labels = (const int*)d_in[1];
    const int*   mask   = (const int*)d_in[2];
    const float* trans  = (const float*)d_in[3];
    const float* strans = (const float*)d_in[4];
    const float* etrans = (const float*)d_in[5];
    float* out = (float*)d_out;

    k_main<<<GRID_MAIN, 256>>>(emit, mask, trans);
    k_score<<<BB, 256>>>(emit, labels, mask, trans, strans, etrans);
    k_final<<<1, 256>>>(emit, out);
}